// round 1
// baseline (speedup 1.0000x reference)
#include <cuda_runtime.h>
#include <cstdint>

#define N_NODES 100000
#define N_EDGES 3200000
#define F_IN    512
#define F_MID   256
#define F_OUT   64
#define NEG_SLOPE 0.01f

// ---------------- scratch (__device__ globals; no allocation allowed) -------
__device__ __align__(16) int   g_deg[N_NODES];
__device__ __align__(16) int   g_rowptr[N_NODES + 1];
__device__ __align__(16) int   g_cursor[N_NODES];
__device__ __align__(16) int   g_csr_src[N_EDGES];
__device__ __align__(16) float g_csr_w1[N_EDGES];
__device__ __align__(16) float g_csr_w2[N_EDGES];
__device__ __align__(16) float g_s1[(size_t)N_NODES * F_MID];  // x @ W1
__device__ __align__(16) float g_h [(size_t)N_NODES * F_MID];  // after agg+bias+leaky
__device__ __align__(16) float g_s2[(size_t)N_NODES * F_OUT];  // h @ W2

// ---------------- CSR construction ------------------------------------------
__global__ void zero_deg_kernel() {
    int i = blockIdx.x * blockDim.x + threadIdx.x;
    if (i < N_NODES) g_deg[i] = 0;
}

__global__ void hist_kernel(const int* __restrict__ dst) {
    int e = blockIdx.x * blockDim.x + threadIdx.x;
    if (e < N_EDGES) atomicAdd(&g_deg[dst[e]], 1);
}

// single-block exclusive scan over g_deg -> g_rowptr / g_cursor
__global__ void scan_kernel() {
    __shared__ int s[1024];
    __shared__ int carry;
    int tid = threadIdx.x;
    if (tid == 0) carry = 0;
    __syncthreads();
    for (int base = 0; base < N_NODES; base += 1024) {
        int i = base + tid;
        int v = (i < N_NODES) ? g_deg[i] : 0;
        s[tid] = v;
        __syncthreads();
        #pragma unroll
        for (int off = 1; off < 1024; off <<= 1) {
            int t = (tid >= off) ? s[tid - off] : 0;
            __syncthreads();
            s[tid] += t;
            __syncthreads();
        }
        int total = s[1023];
        int excl  = s[tid] - v;
        if (i < N_NODES) {
            int start = carry + excl;
            g_rowptr[i] = start;
            g_cursor[i] = start;
        }
        __syncthreads();
        if (tid == 0) carry += total;
        __syncthreads();
    }
    if (threadIdx.x == 0) g_rowptr[N_NODES] = N_EDGES;
}

__global__ void scatter_kernel(const int* __restrict__ src,
                               const int* __restrict__ dst,
                               const float* __restrict__ w1,
                               const float* __restrict__ w2) {
    int e = blockIdx.x * blockDim.x + threadIdx.x;
    if (e < N_EDGES) {
        int d = dst[e];
        int p = atomicAdd(&g_cursor[d], 1);
        g_csr_src[p] = src[e];
        g_csr_w1[p]  = w1[e];
        g_csr_w2[p]  = w2[e];
    }
}

// ---------------- fp32 register-blocked GEMM --------------------------------
// C[M,N] = A[M,K] @ B[K,N], row-major everywhere. BM=128, BN=64, BK=16,
// TM=8, TN=4 -> 256 threads.
template <int KDIM, int NDIM>
__device__ __forceinline__ void gemm_body(const float* __restrict__ A,
                                          const float* __restrict__ B,
                                          float* __restrict__ C, int M) {
    constexpr int BM = 128, BN = 64, BK = 16, TM = 8, TN = 4;
    constexpr int THREADS = (BM / TM) * (BN / TN);  // 256
    __shared__ float As[BK][BM];
    __shared__ float Bs[BK][BN];

    const int tid = threadIdx.x;
    const int m0  = blockIdx.x * BM;
    const int n0  = blockIdx.y * BN;
    const int tx  = tid % (BN / TN);  // 0..15 (n)
    const int ty  = tid / (BN / TN);  // 0..15 (m)

    float acc[TM][TN];
    #pragma unroll
    for (int i = 0; i < TM; i++)
        #pragma unroll
        for (int j = 0; j < TN; j++) acc[i][j] = 0.f;

    for (int k0 = 0; k0 < KDIM; k0 += BK) {
        // load A tile (BM x BK) -> As transposed; 2 float4 per thread
        #pragma unroll
        for (int i = 0; i < (BM * BK / 4) / THREADS; i++) {
            int f   = tid + i * THREADS;
            int row = f / (BK / 4);
            int c4  = f % (BK / 4);
            float4 v = make_float4(0.f, 0.f, 0.f, 0.f);
            if (m0 + row < M)
                v = *reinterpret_cast<const float4*>(
                        &A[(size_t)(m0 + row) * KDIM + k0 + c4 * 4]);
            As[c4 * 4 + 0][row] = v.x;
            As[c4 * 4 + 1][row] = v.y;
            As[c4 * 4 + 2][row] = v.z;
            As[c4 * 4 + 3][row] = v.w;
        }
        // load B tile (BK x BN); 1 float4 per thread
        #pragma unroll
        for (int i = 0; i < (BK * BN / 4) / THREADS; i++) {
            int f   = tid + i * THREADS;
            int row = f / (BN / 4);
            int c4  = f % (BN / 4);
            *reinterpret_cast<float4*>(&Bs[row][c4 * 4]) =
                *reinterpret_cast<const float4*>(
                    &B[(size_t)(k0 + row) * NDIM + n0 + c4 * 4]);
        }
        __syncthreads();

        #pragma unroll
        for (int k = 0; k < BK; k++) {
            float a[TM], b[TN];
            #pragma unroll
            for (int i = 0; i < TM; i += 4) {
                float4 v = *reinterpret_cast<const float4*>(&As[k][ty * TM + i]);
                a[i] = v.x; a[i + 1] = v.y; a[i + 2] = v.z; a[i + 3] = v.w;
            }
            {
                float4 v = *reinterpret_cast<const float4*>(&Bs[k][tx * TN]);
                b[0] = v.x; b[1] = v.y; b[2] = v.z; b[3] = v.w;
            }
            #pragma unroll
            for (int i = 0; i < TM; i++)
                #pragma unroll
                for (int j = 0; j < TN; j++) acc[i][j] += a[i] * b[j];
        }
        __syncthreads();
    }

    #pragma unroll
    for (int i = 0; i < TM; i++) {
        int m = m0 + ty * TM + i;
        if (m < M) {
            float4 v = make_float4(acc[i][0], acc[i][1], acc[i][2], acc[i][3]);
            *reinterpret_cast<float4*>(&C[(size_t)m * NDIM + n0 + tx * TN]) = v;
        }
    }
}

__global__ __launch_bounds__(256) void gemm1_kernel(const float* __restrict__ x,
                                                    const float* __restrict__ W1) {
    gemm_body<F_IN, F_MID>(x, W1, g_s1, N_NODES);
}

__global__ __launch_bounds__(256) void gemm2_kernel(const float* __restrict__ W2) {
    gemm_body<F_MID, F_OUT>(g_h, W2, g_s2, N_NODES);
}

// ---------------- layer-1 aggregation: block per node, thread per feature ---
__global__ __launch_bounds__(256) void agg1_kernel(const float* __restrict__ b1) {
    const int node = blockIdx.x;
    const int f    = threadIdx.x;
    const int beg  = g_rowptr[node];
    const int end  = g_rowptr[node + 1];
    float acc = 0.f;
    int e = beg;
    for (; e + 4 <= end; e += 4) {
        int   s0 = g_csr_src[e],     s1 = g_csr_src[e + 1];
        int   s2 = g_csr_src[e + 2], s3 = g_csr_src[e + 3];
        float w0 = g_csr_w1[e],      w1 = g_csr_w1[e + 1];
        float w2 = g_csr_w1[e + 2],  w3 = g_csr_w1[e + 3];
        float v0 = g_s1[(size_t)s0 * F_MID + f];
        float v1 = g_s1[(size_t)s1 * F_MID + f];
        float v2 = g_s1[(size_t)s2 * F_MID + f];
        float v3 = g_s1[(size_t)s3 * F_MID + f];
        acc += v0 * w0 + v1 * w1 + v2 * w2 + v3 * w3;
    }
    for (; e < end; e++)
        acc += g_s1[(size_t)g_csr_src[e] * F_MID + f] * g_csr_w1[e];
    acc += b1[f];
    g_h[(size_t)node * F_MID + f] = acc > 0.f ? acc : NEG_SLOPE * acc;
}

// ---------------- layer-2 aggregation + bias + log_softmax ------------------
__global__ __launch_bounds__(64) void agg2_kernel(const float* __restrict__ b2,
                                                  float* __restrict__ out) {
    const int node = blockIdx.x;
    const int f    = threadIdx.x;  // 0..63
    const int beg  = g_rowptr[node];
    const int end  = g_rowptr[node + 1];
    float acc = 0.f;
    int e = beg;
    for (; e + 4 <= end; e += 4) {
        int   s0 = g_csr_src[e],     s1 = g_csr_src[e + 1];
        int   s2 = g_csr_src[e + 2], s3 = g_csr_src[e + 3];
        float w0 = g_csr_w2[e],      w1 = g_csr_w2[e + 1];
        float w2 = g_csr_w2[e + 2],  w3 = g_csr_w2[e + 3];
        float v0 = g_s2[(size_t)s0 * F_OUT + f];
        float v1 = g_s2[(size_t)s1 * F_OUT + f];
        float v2 = g_s2[(size_t)s2 * F_OUT + f];
        float v3 = g_s2[(size_t)s3 * F_OUT + f];
        acc += v0 * w0 + v1 * w1 + v2 * w2 + v3 * w3;
    }
    for (; e < end; e++)
        acc += g_s2[(size_t)g_csr_src[e] * F_OUT + f] * g_csr_w2[e];
    acc += b2[f];

    // log_softmax over 64 features (2 warps)
    const unsigned FULL = 0xffffffffu;
    const int wid = f >> 5, lane = f & 31;
    __shared__ float smax[2], ssum[2];

    float m = acc;
    #pragma unroll
    for (int off = 16; off; off >>= 1) m = fmaxf(m, __shfl_xor_sync(FULL, m, off));
    if (lane == 0) smax[wid] = m;
    __syncthreads();
    m = fmaxf(smax[0], smax[1]);

    float ex = expf(acc - m);
    float s = ex;
    #pragma unroll
    for (int off = 16; off; off >>= 1) s += __shfl_xor_sync(FULL, s, off);
    if (lane == 0) ssum[wid] = s;
    __syncthreads();
    s = ssum[0] + ssum[1];

    out[(size_t)node * F_OUT + f] = acc - m - logf(s);
}

// ---------------- launch -----------------------------------------------------
extern "C" void kernel_launch(void* const* d_in, const int* in_sizes, int n_in,
                              void* d_out, int out_size) {
    const float* x   = (const float*)d_in[0];
    const int*   src = (const int*)d_in[1];
    const int*   dst = (const int*)d_in[2];
    const float* w1  = (const float*)d_in[3];
    const float* w2  = (const float*)d_in[4];
    const float* W1  = (const float*)d_in[5];
    const float* b1  = (const float*)d_in[6];
    const float* W2  = (const float*)d_in[7];
    const float* b2  = (const float*)d_in[8];
    float* out = (float*)d_out;

    const int EB = (N_EDGES + 255) / 256;
    const int NB = (N_NODES + 255) / 256;

    zero_deg_kernel<<<NB, 256>>>();
    hist_kernel<<<EB, 256>>>(dst);
    scan_kernel<<<1, 1024>>>();
    scatter_kernel<<<EB, 256>>>(src, dst, w1, w2);

    {
        dim3 grid((N_NODES + 127) / 128, F_MID / 64);
        gemm1_kernel<<<grid, 256>>>(x, W1);
    }
    agg1_kernel<<<N_NODES, F_MID>>>(b1);
    {
        dim3 grid((N_NODES + 127) / 128, F_OUT / 64);
        gemm2_kernel<<<grid, 256>>>(W2);
    }
    agg2_kernel<<<N_NODES, F_OUT>>>(b2, out);
}

// round 6
// speedup vs baseline: 1.3439x; 1.3439x over previous
#include <cuda_runtime.h>
#include <cstdint>

#define N_NODES 100000
#define N_EDGES 3200000
#define F_IN    512
#define F_MID   256
#define F_OUT   64
#define NEG_SLOPE 0.01f

// ---------------- scratch (__device__ globals; no allocation allowed) -------
// NOTE: these must ONLY be referenced from device code, never passed as
// kernel arguments from host code (host sees a bogus shadow address).
__device__ __align__(16) int   g_deg[N_NODES];
__device__ __align__(16) int   g_rowptr[N_NODES + 1];
__device__ __align__(16) int   g_cursor[N_NODES];
__device__ __align__(16) int   g_blksum[512];
__device__ __align__(16) int   g_blkoff[512];
__device__ __align__(16) int   g_csr_src[N_EDGES];
__device__ __align__(16) float g_csr_w1[N_EDGES];
__device__ __align__(16) float g_csr_w2[N_EDGES];
__device__ __align__(16) float g_s1[(size_t)N_NODES * F_MID];  // x @ W1
__device__ __align__(16) float g_h [(size_t)N_NODES * F_MID];  // after agg+bias+leaky
__device__ __align__(16) float g_s2[(size_t)N_NODES * F_OUT];  // h @ W2

// ---------------- CSR construction ------------------------------------------
__global__ void zero_deg_kernel() {
    int i = blockIdx.x * blockDim.x + threadIdx.x;
    if (i < N_NODES) g_deg[i] = 0;
}

__global__ void hist_kernel(const int* __restrict__ dst) {
    int e = blockIdx.x * blockDim.x + threadIdx.x;
    if (e < N_EDGES) atomicAdd(&g_deg[dst[e]], 1);
}

// 3-phase parallel exclusive scan of g_deg -> g_rowptr / g_cursor
__global__ void scan_part_kernel() {            // grid = NB, block = 256
    __shared__ int warp_tot[8];
    const int b = blockIdx.x, tid = threadIdx.x;
    const int lane = tid & 31, w = tid >> 5;
    const int i = b * 256 + tid;
    int v = (i < N_NODES) ? g_deg[i] : 0;
    int x = v;
    #pragma unroll
    for (int off = 1; off < 32; off <<= 1) {
        int y = __shfl_up_sync(0xffffffffu, x, off);
        if (lane >= off) x += y;
    }
    if (lane == 31) warp_tot[w] = x;
    __syncthreads();
    if (w == 0) {
        int t = (lane < 8) ? warp_tot[lane] : 0;
        #pragma unroll
        for (int off = 1; off < 8; off <<= 1) {
            int y = __shfl_up_sync(0xffffffffu, t, off);
            if (lane >= off) t += y;
        }
        if (lane < 8) warp_tot[lane] = t;   // inclusive warp totals
    }
    __syncthreads();
    int excl = x - v + (w > 0 ? warp_tot[w - 1] : 0);
    if (i < N_NODES) g_rowptr[i] = excl;    // block-local exclusive
    if (tid == 255) g_blksum[b] = excl + v; // block total
}

__global__ void scan_blk_kernel() {             // 1 block, 512 threads
    __shared__ int s[512];
    const int tid = threadIdx.x;
    const int nb = (N_NODES + 255) / 256;
    int v = (tid < nb) ? g_blksum[tid] : 0;
    s[tid] = v;
    __syncthreads();
    #pragma unroll
    for (int off = 1; off < 512; off <<= 1) {
        int t = (tid >= off) ? s[tid - off] : 0;
        __syncthreads();
        s[tid] += t;
        __syncthreads();
    }
    g_blkoff[tid] = s[tid] - v;                 // exclusive
}

__global__ void scan_add_kernel() {             // grid = NB, block = 256
    const int b = blockIdx.x;
    const int i = b * 256 + threadIdx.x;
    if (i < N_NODES) {
        int r = g_rowptr[i] + g_blkoff[b];
        g_rowptr[i] = r;
        g_cursor[i] = r;
    }
    if (i == 0) g_rowptr[N_NODES] = N_EDGES;
}

__global__ void scatter_kernel(const int* __restrict__ src,
                               const int* __restrict__ dst,
                               const float* __restrict__ w1,
                               const float* __restrict__ w2) {
    int e = blockIdx.x * blockDim.x + threadIdx.x;
    if (e < N_EDGES) {
        int d = dst[e];
        int p = atomicAdd(&g_cursor[d], 1);
        g_csr_src[p] = src[e];
        g_csr_w1[p]  = w1[e];
        g_csr_w2[p]  = w2[e];
    }
}

// ---------------- TF32 tensor-core GEMM (layer 1) ----------------------------
// Round-to-nearest emulation of tf32 conversion in plain integer ops.
__device__ __forceinline__ uint32_t f2tf32(float f) {
    uint32_t u = __float_as_uint(f);
    u += 0xFFFu + ((u >> 13) & 1u);
    return u & 0xFFFFE000u;
}

__device__ __forceinline__ void mma_tf32(float* c, const uint32_t* a, const uint32_t* b) {
    asm volatile(
        "mma.sync.aligned.m16n8k8.row.col.f32.tf32.tf32.f32 "
        "{%0,%1,%2,%3}, {%4,%5,%6,%7}, {%8,%9}, {%0,%1,%2,%3};"
        : "+f"(c[0]), "+f"(c[1]), "+f"(c[2]), "+f"(c[3])
        : "r"(a[0]), "r"(a[1]), "r"(a[2]), "r"(a[3]), "r"(b[0]), "r"(b[1]));
}

// g_s1[100000,256] = A[100000,512] @ B[512,256]. BM=128, BN=128, BK=16.
// 256 threads = 8 warps laid out 4(M) x 2(N); warp tile 32x64.
// Plain ld.global.v4 -> st.shared staging, single buffer, full syncs.
// Output written to g_s1 via device-side global reference.
__global__ __launch_bounds__(256) void gemm1_tf32_kernel(const float* __restrict__ A,
                                                         const float* __restrict__ B) {
    constexpr int KDIM = F_IN, NDIM = F_MID, M = N_NODES;
    constexpr int BM = 128, BK = 16;
    constexpr int BKp = 20;    // padded A stride
    constexpr int BNp = 132;   // padded B stride

    __shared__ float As[BM * BKp];
    __shared__ float Bs[BK * BNp];

    const int tid  = threadIdx.x;
    const int lane = tid & 31;
    const int warp = tid >> 5;
    const int wm   = (warp & 3) * 32;   // warp M origin
    const int wn   = (warp >> 2) * 64;  // warp N origin
    const int m0   = blockIdx.x * BM;
    const int n0   = blockIdx.y * 128;

    float acc[2][8][4];
    #pragma unroll
    for (int mt = 0; mt < 2; mt++)
        #pragma unroll
        for (int nt = 0; nt < 8; nt++)
            #pragma unroll
            for (int j = 0; j < 4; j++) acc[mt][nt][j] = 0.f;

    for (int k0 = 0; k0 < KDIM; k0 += BK) {
        __syncthreads();   // previous-iteration reads done before overwrite
        // stage A tile: 128 rows x 16 cols = 512 float4, 2 per thread
        #pragma unroll
        for (int i = 0; i < 2; i++) {
            int c   = tid + i * 256;
            int row = c >> 2;
            int c4  = c & 3;
            float4 v = make_float4(0.f, 0.f, 0.f, 0.f);
            if (m0 + row < M)
                v = *reinterpret_cast<const float4*>(
                        &A[(size_t)(m0 + row) * KDIM + k0 + c4 * 4]);
            *reinterpret_cast<float4*>(&As[row * BKp + c4 * 4]) = v;
        }
        // stage B tile: 16 rows x 128 cols = 512 float4, 2 per thread
        #pragma unroll
        for (int i = 0; i < 2; i++) {
            int c   = tid + i * 256;
            int row = c >> 5;
            int c4  = c & 31;
            float4 v = *reinterpret_cast<const float4*>(
                           &B[(size_t)(k0 + row) * NDIM + n0 + c4 * 4]);
            *reinterpret_cast<float4*>(&Bs[row * BNp + c4 * 4]) = v;
        }
        __syncthreads();

        #pragma unroll
        for (int kk = 0; kk < BK; kk += 8) {
            uint32_t af[2][4], bf[8][2];
            #pragma unroll
            for (int mt = 0; mt < 2; mt++) {
                int r0 = wm + mt * 16 + (lane >> 2);
                int c0 = kk + (lane & 3);
                af[mt][0] = f2tf32(As[r0 * BKp + c0]);
                af[mt][1] = f2tf32(As[(r0 + 8) * BKp + c0]);
                af[mt][2] = f2tf32(As[r0 * BKp + c0 + 4]);
                af[mt][3] = f2tf32(As[(r0 + 8) * BKp + c0 + 4]);
            }
            #pragma unroll
            for (int nt = 0; nt < 8; nt++) {
                int col = wn + nt * 8 + (lane >> 2);
                int r   = kk + (lane & 3);
                bf[nt][0] = f2tf32(Bs[r * BNp + col]);
                bf[nt][1] = f2tf32(Bs[(r + 4) * BNp + col]);
            }
            #pragma unroll
            for (int mt = 0; mt < 2; mt++)
                #pragma unroll
                for (int nt = 0; nt < 8; nt++)
                    mma_tf32(acc[mt][nt], af[mt], bf[nt]);
        }
    }

    #pragma unroll
    for (int mt = 0; mt < 2; mt++) {
        #pragma unroll
        for (int nt = 0; nt < 8; nt++) {
            int r0  = m0 + wm + mt * 16 + (lane >> 2);
            int col = n0 + wn + nt * 8 + 2 * (lane & 3);
            if (r0 < M) {
                float2 v = make_float2(acc[mt][nt][0], acc[mt][nt][1]);
                *reinterpret_cast<float2*>(&g_s1[(size_t)r0 * NDIM + col]) = v;
            }
            if (r0 + 8 < M) {
                float2 v = make_float2(acc[mt][nt][2], acc[mt][nt][3]);
                *reinterpret_cast<float2*>(&g_s1[(size_t)(r0 + 8) * NDIM + col]) = v;
            }
        }
    }
}

// ---------------- fp32 SIMT GEMM (layer 2, proven in R0) ---------------------
template <int KDIM, int NDIM>
__device__ __forceinline__ void gemm_body(const float* __restrict__ A,
                                          const float* __restrict__ B,
                                          float* __restrict__ C, int M) {
    constexpr int BM = 128, BN = 64, BK = 16, TM = 8, TN = 4;
    constexpr int THREADS = (BM / TM) * (BN / TN);  // 256
    __shared__ float As[BK][BM];
    __shared__ float Bs[BK][BN];

    const int tid = threadIdx.x;
    const int m0  = blockIdx.x * BM;
    const int n0  = blockIdx.y * BN;
    const int tx  = tid % (BN / TN);
    const int ty  = tid / (BN / TN);

    float acc[TM][TN];
    #pragma unroll
    for (int i = 0; i < TM; i++)
        #pragma unroll
        for (int j = 0; j < TN; j++) acc[i][j] = 0.f;

    for (int k0 = 0; k0 < KDIM; k0 += BK) {
        #pragma unroll
        for (int i = 0; i < (BM * BK / 4) / THREADS; i++) {
            int f   = tid + i * THREADS;
            int row = f / (BK / 4);
            int c4  = f % (BK / 4);
            float4 v = make_float4(0.f, 0.f, 0.f, 0.f);
            if (m0 + row < M)
                v = *reinterpret_cast<const float4*>(
                        &A[(size_t)(m0 + row) * KDIM + k0 + c4 * 4]);
            As[c4 * 4 + 0][row] = v.x;
            As[c4 * 4 + 1][row] = v.y;
            As[c4 * 4 + 2][row] = v.z;
            As[c4 * 4 + 3][row] = v.w;
        }
        #pragma unroll
        for (int i = 0; i < (BK * BN / 4) / THREADS; i++) {
            int f   = tid + i * THREADS;
            int row = f / (BN / 4);
            int c4  = f % (BN / 4);
            *reinterpret_cast<float4*>(&Bs[row][c4 * 4]) =
                *reinterpret_cast<const float4*>(
                    &B[(size_t)(k0 + row) * NDIM + n0 + c4 * 4]);
        }
        __syncthreads();

        #pragma unroll
        for (int k = 0; k < BK; k++) {
            float a[TM], b[TN];
            #pragma unroll
            for (int i = 0; i < TM; i += 4) {
                float4 v = *reinterpret_cast<const float4*>(&As[k][ty * TM + i]);
                a[i] = v.x; a[i + 1] = v.y; a[i + 2] = v.z; a[i + 3] = v.w;
            }
            {
                float4 v = *reinterpret_cast<const float4*>(&Bs[k][tx * TN]);
                b[0] = v.x; b[1] = v.y; b[2] = v.z; b[3] = v.w;
            }
            #pragma unroll
            for (int i = 0; i < TM; i++)
                #pragma unroll
                for (int j = 0; j < TN; j++) acc[i][j] += a[i] * b[j];
        }
        __syncthreads();
    }

    #pragma unroll
    for (int i = 0; i < TM; i++) {
        int m = m0 + ty * TM + i;
        if (m < M) {
            float4 v = make_float4(acc[i][0], acc[i][1], acc[i][2], acc[i][3]);
            *reinterpret_cast<float4*>(&C[(size_t)m * NDIM + n0 + tx * TN]) = v;
        }
    }
}

__global__ __launch_bounds__(256) void gemm2_kernel(const float* __restrict__ W2) {
    gemm_body<F_MID, F_OUT>(g_h, W2, g_s2, N_NODES);
}

// ---------------- layer-1 aggregation: block per node, thread per feature ---
__global__ __launch_bounds__(256) void agg1_kernel(const float* __restrict__ b1) {
    const int node = blockIdx.x;
    const int f    = threadIdx.x;
    const int beg  = g_rowptr[node];
    const int end  = g_rowptr[node + 1];
    float acc = 0.f;
    int e = beg;
    for (; e + 4 <= end; e += 4) {
        int   s0 = g_csr_src[e],     s1 = g_csr_src[e + 1];
        int   s2 = g_csr_src[e + 2], s3 = g_csr_src[e + 3];
        float w0 = g_csr_w1[e],      w1 = g_csr_w1[e + 1];
        float w2 = g_csr_w1[e + 2],  w3 = g_csr_w1[e + 3];
        float v0 = g_s1[(size_t)s0 * F_MID + f];
        float v1 = g_s1[(size_t)s1 * F_MID + f];
        float v2 = g_s1[(size_t)s2 * F_MID + f];
        float v3 = g_s1[(size_t)s3 * F_MID + f];
        acc += v0 * w0 + v1 * w1 + v2 * w2 + v3 * w3;
    }
    for (; e < end; e++)
        acc += g_s1[(size_t)g_csr_src[e] * F_MID + f] * g_csr_w1[e];
    acc += b1[f];
    g_h[(size_t)node * F_MID + f] = acc > 0.f ? acc : NEG_SLOPE * acc;
}

// ---------------- layer-2 aggregation + bias + log_softmax ------------------
__global__ __launch_bounds__(64) void agg2_kernel(const float* __restrict__ b2,
                                                  float* __restrict__ out) {
    const int node = blockIdx.x;
    const int f    = threadIdx.x;  // 0..63
    const int beg  = g_rowptr[node];
    const int end  = g_rowptr[node + 1];
    float acc = 0.f;
    int e = beg;
    for (; e + 4 <= end; e += 4) {
        int   s0 = g_csr_src[e],     s1 = g_csr_src[e + 1];
        int   s2 = g_csr_src[e + 2], s3 = g_csr_src[e + 3];
        float w0 = g_csr_w2[e],      w1 = g_csr_w2[e + 1];
        float w2 = g_csr_w2[e + 2],  w3 = g_csr_w2[e + 3];
        float v0 = g_s2[(size_t)s0 * F_OUT + f];
        float v1 = g_s2[(size_t)s1 * F_OUT + f];
        float v2 = g_s2[(size_t)s2 * F_OUT + f];
        float v3 = g_s2[(size_t)s3 * F_OUT + f];
        acc += v0 * w0 + v1 * w1 + v2 * w2 + v3 * w3;
    }
    for (; e < end; e++)
        acc += g_s2[(size_t)g_csr_src[e] * F_OUT + f] * g_csr_w2[e];
    acc += b2[f];

    const unsigned FULL = 0xffffffffu;
    const int wid = f >> 5, lane = f & 31;
    __shared__ float smax[2], ssum[2];

    float m = acc;
    #pragma unroll
    for (int off = 16; off; off >>= 1) m = fmaxf(m, __shfl_xor_sync(FULL, m, off));
    if (lane == 0) smax[wid] = m;
    __syncthreads();
    m = fmaxf(smax[0], smax[1]);

    float ex = expf(acc - m);
    float s = ex;
    #pragma unroll
    for (int off = 16; off; off >>= 1) s += __shfl_xor_sync(FULL, s, off);
    if (lane == 0) ssum[wid] = s;
    __syncthreads();
    s = ssum[0] + ssum[1];

    out[(size_t)node * F_OUT + f] = acc - m - logf(s);
}

// ---------------- launch -----------------------------------------------------
extern "C" void kernel_launch(void* const* d_in, const int* in_sizes, int n_in,
                              void* d_out, int out_size) {
    const float* x   = (const float*)d_in[0];
    const int*   src = (const int*)d_in[1];
    const int*   dst = (const int*)d_in[2];
    const float* w1  = (const float*)d_in[3];
    const float* w2  = (const float*)d_in[4];
    const float* W1  = (const float*)d_in[5];
    const float* b1  = (const float*)d_in[6];
    const float* W2  = (const float*)d_in[7];
    const float* b2  = (const float*)d_in[8];
    float* out = (float*)d_out;

    const int EB = (N_EDGES + 255) / 256;
    const int NB = (N_NODES + 255) / 256;

    zero_deg_kernel<<<NB, 256>>>();                 // launch 0
    hist_kernel<<<EB, 256>>>(dst);                  // launch 1
    scan_part_kernel<<<NB, 256>>>();                // launch 2
    scan_blk_kernel<<<1, 512>>>();                  // launch 3
    scan_add_kernel<<<NB, 256>>>();                 // launch 4
    {                                               // launch 5 (ncu -s 5 -c 1)
        dim3 grid((N_NODES + 127) / 128, F_MID / 128);
        gemm1_tf32_kernel<<<grid, 256>>>(x, W1);
    }
    scatter_kernel<<<EB, 256>>>(src, dst, w1, w2);  // launch 6
    agg1_kernel<<<N_NODES, F_MID>>>(b1);            // launch 7
    {
        dim3 grid((N_NODES + 127) / 128, 1);
        gemm2_kernel<<<grid, 256>>>(W2);
    }
    agg2_kernel<<<N_NODES, F_OUT>>>(b2, out);
}

// round 7
// speedup vs baseline: 1.8793x; 1.3984x over previous
#include <cuda_runtime.h>
#include <cuda_fp16.h>
#include <cstdint>

#define N_NODES 100000
#define N_EDGES 3200000
#define F_IN    512
#define F_MID   256
#define F_OUT   64
#define NEG_SLOPE 0.01f

// ---------------- scratch (__device__ globals; no allocation allowed) -------
// NOTE: referenced ONLY from device code, never passed as kernel args from host.
__device__ __align__(16) int     g_deg[N_NODES];
__device__ __align__(16) int     g_rowptr[N_NODES + 1];
__device__ __align__(16) int     g_cursor[N_NODES];
__device__ __align__(16) int     g_blksum[512];
__device__ __align__(16) int     g_blkoff[512];
__device__ __align__(16) int     g_csr_src[N_EDGES];
__device__ __align__(16) float   g_csr_w1[N_EDGES];
__device__ __align__(16) float   g_csr_w2[N_EDGES];
__device__ __align__(16) __half2 g_s1h[(size_t)N_NODES * (F_MID / 2)]; // x@W1, fp16
__device__ __align__(16) float   g_h [(size_t)N_NODES * F_MID];  // after agg+bias+leaky
__device__ __align__(16) float   g_s2[(size_t)N_NODES * F_OUT];  // h @ W2

// ---------------- CSR construction ------------------------------------------
__global__ void zero_deg_kernel() {
    int i = blockIdx.x * blockDim.x + threadIdx.x;
    if (i < N_NODES) g_deg[i] = 0;
}

__global__ void hist_kernel(const int* __restrict__ dst) {
    int e = blockIdx.x * blockDim.x + threadIdx.x;
    if (e < N_EDGES) atomicAdd(&g_deg[dst[e]], 1);
}

// 3-phase parallel exclusive scan of g_deg -> g_rowptr / g_cursor
__global__ void scan_part_kernel() {            // grid = NB, block = 256
    __shared__ int warp_tot[8];
    const int b = blockIdx.x, tid = threadIdx.x;
    const int lane = tid & 31, w = tid >> 5;
    const int i = b * 256 + tid;
    int v = (i < N_NODES) ? g_deg[i] : 0;
    int x = v;
    #pragma unroll
    for (int off = 1; off < 32; off <<= 1) {
        int y = __shfl_up_sync(0xffffffffu, x, off);
        if (lane >= off) x += y;
    }
    if (lane == 31) warp_tot[w] = x;
    __syncthreads();
    if (w == 0) {
        int t = (lane < 8) ? warp_tot[lane] : 0;
        #pragma unroll
        for (int off = 1; off < 8; off <<= 1) {
            int y = __shfl_up_sync(0xffffffffu, t, off);
            if (lane >= off) t += y;
        }
        if (lane < 8) warp_tot[lane] = t;   // inclusive warp totals
    }
    __syncthreads();
    int excl = x - v + (w > 0 ? warp_tot[w - 1] : 0);
    if (i < N_NODES) g_rowptr[i] = excl;    // block-local exclusive
    if (tid == 255) g_blksum[b] = excl + v; // block total
}

__global__ void scan_blk_kernel() {             // 1 block, 512 threads
    __shared__ int s[512];
    const int tid = threadIdx.x;
    const int nb = (N_NODES + 255) / 256;
    int v = (tid < nb) ? g_blksum[tid] : 0;
    s[tid] = v;
    __syncthreads();
    #pragma unroll
    for (int off = 1; off < 512; off <<= 1) {
        int t = (tid >= off) ? s[tid - off] : 0;
        __syncthreads();
        s[tid] += t;
        __syncthreads();
    }
    g_blkoff[tid] = s[tid] - v;                 // exclusive
}

__global__ void scan_add_kernel() {             // grid = NB, block = 256
    const int b = blockIdx.x;
    const int i = b * 256 + threadIdx.x;
    if (i < N_NODES) {
        int r = g_rowptr[i] + g_blkoff[b];
        g_rowptr[i] = r;
        g_cursor[i] = r;
    }
    if (i == 0) g_rowptr[N_NODES] = N_EDGES;
}

__global__ void scatter_kernel(const int* __restrict__ src,
                               const int* __restrict__ dst,
                               const float* __restrict__ w1,
                               const float* __restrict__ w2) {
    int e = blockIdx.x * blockDim.x + threadIdx.x;
    if (e < N_EDGES) {
        int d = dst[e];
        int p = atomicAdd(&g_cursor[d], 1);
        g_csr_src[p] = src[e];
        g_csr_w1[p]  = w1[e];
        g_csr_w2[p]  = w2[e];
    }
}

// ---------------- TF32 tensor-core GEMM helpers ------------------------------
__device__ __forceinline__ uint32_t f2tf32(float f) {
    uint32_t u = __float_as_uint(f);
    u += 0xFFFu + ((u >> 13) & 1u);
    return u & 0xFFFFE000u;
}

__device__ __forceinline__ void mma_tf32(float* c, const uint32_t* a, const uint32_t* b) {
    asm volatile(
        "mma.sync.aligned.m16n8k8.row.col.f32.tf32.tf32.f32 "
        "{%0,%1,%2,%3}, {%4,%5,%6,%7}, {%8,%9}, {%0,%1,%2,%3};"
        : "+f"(c[0]), "+f"(c[1]), "+f"(c[2]), "+f"(c[3])
        : "r"(a[0]), "r"(a[1]), "r"(a[2]), "r"(a[3]), "r"(b[0]), "r"(b[1]));
}

// ---------------- GEMM1: g_s1h[100000,256](fp16) = x @ W1 --------------------
// BM=128, BN=128, BK=16; 8 warps 4(M) x 2(N); warp tile 32x64.
__global__ __launch_bounds__(256) void gemm1_tf32_kernel(const float* __restrict__ A,
                                                         const float* __restrict__ B) {
    constexpr int KDIM = F_IN, NDIM = F_MID, M = N_NODES;
    constexpr int BM = 128, BK = 16;
    constexpr int BKp = 20;
    constexpr int BNp = 132;

    __shared__ float As[BM * BKp];
    __shared__ float Bs[BK * BNp];

    const int tid  = threadIdx.x;
    const int lane = tid & 31;
    const int warp = tid >> 5;
    const int wm   = (warp & 3) * 32;
    const int wn   = (warp >> 2) * 64;
    const int m0   = blockIdx.x * BM;
    const int n0   = blockIdx.y * 128;

    float acc[2][8][4];
    #pragma unroll
    for (int mt = 0; mt < 2; mt++)
        #pragma unroll
        for (int nt = 0; nt < 8; nt++)
            #pragma unroll
            for (int j = 0; j < 4; j++) acc[mt][nt][j] = 0.f;

    for (int k0 = 0; k0 < KDIM; k0 += BK) {
        __syncthreads();
        #pragma unroll
        for (int i = 0; i < 2; i++) {       // A tile: 512 float4
            int c   = tid + i * 256;
            int row = c >> 2;
            int c4  = c & 3;
            float4 v = make_float4(0.f, 0.f, 0.f, 0.f);
            if (m0 + row < M)
                v = *reinterpret_cast<const float4*>(
                        &A[(size_t)(m0 + row) * KDIM + k0 + c4 * 4]);
            *reinterpret_cast<float4*>(&As[row * BKp + c4 * 4]) = v;
        }
        #pragma unroll
        for (int i = 0; i < 2; i++) {       // B tile: 512 float4
            int c   = tid + i * 256;
            int row = c >> 5;
            int c4  = c & 31;
            float4 v = *reinterpret_cast<const float4*>(
                           &B[(size_t)(k0 + row) * NDIM + n0 + c4 * 4]);
            *reinterpret_cast<float4*>(&Bs[row * BNp + c4 * 4]) = v;
        }
        __syncthreads();

        #pragma unroll
        for (int kk = 0; kk < BK; kk += 8) {
            uint32_t af[2][4], bf[8][2];
            #pragma unroll
            for (int mt = 0; mt < 2; mt++) {
                int r0 = wm + mt * 16 + (lane >> 2);
                int c0 = kk + (lane & 3);
                af[mt][0] = f2tf32(As[r0 * BKp + c0]);
                af[mt][1] = f2tf32(As[(r0 + 8) * BKp + c0]);
                af[mt][2] = f2tf32(As[r0 * BKp + c0 + 4]);
                af[mt][3] = f2tf32(As[(r0 + 8) * BKp + c0 + 4]);
            }
            #pragma unroll
            for (int nt = 0; nt < 8; nt++) {
                int col = wn + nt * 8 + (lane >> 2);
                int r   = kk + (lane & 3);
                bf[nt][0] = f2tf32(Bs[r * BNp + col]);
                bf[nt][1] = f2tf32(Bs[(r + 4) * BNp + col]);
            }
            #pragma unroll
            for (int mt = 0; mt < 2; mt++)
                #pragma unroll
                for (int nt = 0; nt < 8; nt++)
                    mma_tf32(acc[mt][nt], af[mt], bf[nt]);
        }
    }

    // epilogue: convert to fp16 pairs; col is even so (col, col+1) -> one half2
    #pragma unroll
    for (int mt = 0; mt < 2; mt++) {
        #pragma unroll
        for (int nt = 0; nt < 8; nt++) {
            int r0  = m0 + wm + mt * 16 + (lane >> 2);
            int col = n0 + wn + nt * 8 + 2 * (lane & 3);
            if (r0 < M)
                g_s1h[((size_t)r0 * NDIM + col) / 2] =
                    __float22half2_rn(make_float2(acc[mt][nt][0], acc[mt][nt][1]));
            if (r0 + 8 < M)
                g_s1h[((size_t)(r0 + 8) * NDIM + col) / 2] =
                    __float22half2_rn(make_float2(acc[mt][nt][2], acc[mt][nt][3]));
        }
    }
}

// ---------------- GEMM2: g_s2[100000,64] = g_h @ W2 (tf32) -------------------
// BM=128, BN=64, BK=16; 8 warps 4(M) x 2(N); warp tile 32x32.
__global__ __launch_bounds__(256) void gemm2_tf32_kernel(const float* __restrict__ B) {
    constexpr int KDIM = F_MID, NDIM = F_OUT, M = N_NODES;
    constexpr int BM = 128, BK = 16;
    constexpr int BKp = 20;
    constexpr int BNp = 68;

    __shared__ float As[BM * BKp];
    __shared__ float Bs[BK * BNp];

    const int tid  = threadIdx.x;
    const int lane = tid & 31;
    const int warp = tid >> 5;
    const int wm   = (warp & 3) * 32;
    const int wn   = (warp >> 2) * 32;
    const int m0   = blockIdx.x * BM;

    float acc[2][4][4];
    #pragma unroll
    for (int mt = 0; mt < 2; mt++)
        #pragma unroll
        for (int nt = 0; nt < 4; nt++)
            #pragma unroll
            for (int j = 0; j < 4; j++) acc[mt][nt][j] = 0.f;

    for (int k0 = 0; k0 < KDIM; k0 += BK) {
        __syncthreads();
        #pragma unroll
        for (int i = 0; i < 2; i++) {       // A tile: 512 float4
            int c   = tid + i * 256;
            int row = c >> 2;
            int c4  = c & 3;
            float4 v = make_float4(0.f, 0.f, 0.f, 0.f);
            if (m0 + row < M)
                v = *reinterpret_cast<const float4*>(
                        &g_h[(size_t)(m0 + row) * KDIM + k0 + c4 * 4]);
            *reinterpret_cast<float4*>(&As[row * BKp + c4 * 4]) = v;
        }
        {                                   // B tile: 16x64 = 256 float4
            int row = tid >> 4;
            int c4  = tid & 15;
            *reinterpret_cast<float4*>(&Bs[row * BNp + c4 * 4]) =
                *reinterpret_cast<const float4*>(
                    &B[(size_t)(k0 + row) * NDIM + c4 * 4]);
        }
        __syncthreads();

        #pragma unroll
        for (int kk = 0; kk < BK; kk += 8) {
            uint32_t af[2][4], bf[4][2];
            #pragma unroll
            for (int mt = 0; mt < 2; mt++) {
                int r0 = wm + mt * 16 + (lane >> 2);
                int c0 = kk + (lane & 3);
                af[mt][0] = f2tf32(As[r0 * BKp + c0]);
                af[mt][1] = f2tf32(As[(r0 + 8) * BKp + c0]);
                af[mt][2] = f2tf32(As[r0 * BKp + c0 + 4]);
                af[mt][3] = f2tf32(As[(r0 + 8) * BKp + c0 + 4]);
            }
            #pragma unroll
            for (int nt = 0; nt < 4; nt++) {
                int col = wn + nt * 8 + (lane >> 2);
                int r   = kk + (lane & 3);
                bf[nt][0] = f2tf32(Bs[r * BNp + col]);
                bf[nt][1] = f2tf32(Bs[(r + 4) * BNp + col]);
            }
            #pragma unroll
            for (int mt = 0; mt < 2; mt++)
                #pragma unroll
                for (int nt = 0; nt < 4; nt++)
                    mma_tf32(acc[mt][nt], af[mt], bf[nt]);
        }
    }

    #pragma unroll
    for (int mt = 0; mt < 2; mt++) {
        #pragma unroll
        for (int nt = 0; nt < 4; nt++) {
            int r0  = m0 + wm + mt * 16 + (lane >> 2);
            int col = wn + nt * 8 + 2 * (lane & 3);
            if (r0 < M)
                *reinterpret_cast<float2*>(&g_s2[(size_t)r0 * NDIM + col]) =
                    make_float2(acc[mt][nt][0], acc[mt][nt][1]);
            if (r0 + 8 < M)
                *reinterpret_cast<float2*>(&g_s2[(size_t)(r0 + 8) * NDIM + col]) =
                    make_float2(acc[mt][nt][2], acc[mt][nt][3]);
        }
    }
}

// ---------------- layer-1 aggregation: 128 threads/node, half2 gathers ------
__global__ __launch_bounds__(128) void agg1_kernel(const float* __restrict__ b1) {
    const int node = blockIdx.x;
    const int f2   = threadIdx.x;           // 0..127, handles features 2f2, 2f2+1
    const int beg  = g_rowptr[node];
    const int end  = g_rowptr[node + 1];
    float acc0 = 0.f, acc1 = 0.f;
    int e = beg;
    for (; e + 4 <= end; e += 4) {
        int   s0 = g_csr_src[e],     s1 = g_csr_src[e + 1];
        int   s2 = g_csr_src[e + 2], s3 = g_csr_src[e + 3];
        float w0 = g_csr_w1[e],      w1 = g_csr_w1[e + 1];
        float w2 = g_csr_w1[e + 2],  w3 = g_csr_w1[e + 3];
        float2 v0 = __half22float2(g_s1h[(size_t)s0 * (F_MID / 2) + f2]);
        float2 v1 = __half22float2(g_s1h[(size_t)s1 * (F_MID / 2) + f2]);
        float2 v2 = __half22float2(g_s1h[(size_t)s2 * (F_MID / 2) + f2]);
        float2 v3 = __half22float2(g_s1h[(size_t)s3 * (F_MID / 2) + f2]);
        acc0 += v0.x * w0 + v1.x * w1 + v2.x * w2 + v3.x * w3;
        acc1 += v0.y * w0 + v1.y * w1 + v2.y * w2 + v3.y * w3;
    }
    for (; e < end; e++) {
        float  w = g_csr_w1[e];
        float2 v = __half22float2(g_s1h[(size_t)g_csr_src[e] * (F_MID / 2) + f2]);
        acc0 += v.x * w;
        acc1 += v.y * w;
    }
    acc0 += b1[2 * f2];
    acc1 += b1[2 * f2 + 1];
    g_h[(size_t)node * F_MID + 2 * f2]     = acc0 > 0.f ? acc0 : NEG_SLOPE * acc0;
    g_h[(size_t)node * F_MID + 2 * f2 + 1] = acc1 > 0.f ? acc1 : NEG_SLOPE * acc1;
}

// ---------------- layer-2 aggregation + bias + log_softmax ------------------
__global__ __launch_bounds__(64) void agg2_kernel(const float* __restrict__ b2,
                                                  float* __restrict__ out) {
    const int node = blockIdx.x;
    const int f    = threadIdx.x;  // 0..63
    const int beg  = g_rowptr[node];
    const int end  = g_rowptr[node + 1];
    float acc = 0.f;
    int e = beg;
    for (; e + 4 <= end; e += 4) {
        int   s0 = g_csr_src[e],     s1 = g_csr_src[e + 1];
        int   s2 = g_csr_src[e + 2], s3 = g_csr_src[e + 3];
        float w0 = g_csr_w2[e],      w1 = g_csr_w2[e + 1];
        float w2 = g_csr_w2[e + 2],  w3 = g_csr_w2[e + 3];
        float v0 = g_s2[(size_t)s0 * F_OUT + f];
        float v1 = g_s2[(size_t)s1 * F_OUT + f];
        float v2 = g_s2[(size_t)s2 * F_OUT + f];
        float v3 = g_s2[(size_t)s3 * F_OUT + f];
        acc += v0 * w0 + v1 * w1 + v2 * w2 + v3 * w3;
    }
    for (; e < end; e++)
        acc += g_s2[(size_t)g_csr_src[e] * F_OUT + f] * g_csr_w2[e];
    acc += b2[f];

    const unsigned FULL = 0xffffffffu;
    const int wid = f >> 5, lane = f & 31;
    __shared__ float smax[2], ssum[2];

    float m = acc;
    #pragma unroll
    for (int off = 16; off; off >>= 1) m = fmaxf(m, __shfl_xor_sync(FULL, m, off));
    if (lane == 0) smax[wid] = m;
    __syncthreads();
    m = fmaxf(smax[0], smax[1]);

    float ex = expf(acc - m);
    float s = ex;
    #pragma unroll
    for (int off = 16; off; off >>= 1) s += __shfl_xor_sync(FULL, s, off);
    if (lane == 0) ssum[wid] = s;
    __syncthreads();
    s = ssum[0] + ssum[1];

    out[(size_t)node * F_OUT + f] = acc - m - logf(s);
}

// ---------------- launch -----------------------------------------------------
extern "C" void kernel_launch(void* const* d_in, const int* in_sizes, int n_in,
                              void* d_out, int out_size) {
    const float* x   = (const float*)d_in[0];
    const int*   src = (const int*)d_in[1];
    const int*   dst = (const int*)d_in[2];
    const float* w1  = (const float*)d_in[3];
    const float* w2  = (const float*)d_in[4];
    const float* W1  = (const float*)d_in[5];
    const float* b1  = (const float*)d_in[6];
    const float* W2  = (const float*)d_in[7];
    const float* b2  = (const float*)d_in[8];
    float* out = (float*)d_out;

    const int EB = (N_EDGES + 255) / 256;
    const int NB = (N_NODES + 255) / 256;

    zero_deg_kernel<<<NB, 256>>>();                 // launch 0
    hist_kernel<<<EB, 256>>>(dst);                  // launch 1
    scan_part_kernel<<<NB, 256>>>();                // launch 2
    scan_blk_kernel<<<1, 512>>>();                  // launch 3
    scan_add_kernel<<<NB, 256>>>();                 // launch 4
    {                                               // launch 5
        dim3 grid((N_NODES + 127) / 128, F_MID / 128);
        gemm1_tf32_kernel<<<grid, 256>>>(x, W1);
    }
    scatter_kernel<<<EB, 256>>>(src, dst, w1, w2);  // launch 6
    agg1_kernel<<<N_NODES, 128>>>(b1);              // launch 7
    gemm2_tf32_kernel<<<(N_NODES + 127) / 128, 256>>>(W2);
    agg2_kernel<<<N_NODES, F_OUT>>>(b2, out);
}

// round 8
// speedup vs baseline: 2.1035x; 1.1193x over previous
#include <cuda_runtime.h>
#include <cuda_fp16.h>
#include <cstdint>

#define N_NODES 100000
#define N_EDGES 3200000
#define F_IN    512
#define F_MID   256
#define F_OUT   64
#define NEG_SLOPE 0.01f

// ---------------- scratch (__device__ globals; no allocation allowed) -------
// NOTE: referenced ONLY from device code, never passed as kernel args from host.
__device__ __align__(16) int     g_deg[N_NODES];
__device__ __align__(16) int     g_rowptr[N_NODES + 1];
__device__ __align__(16) int     g_cursor[N_NODES];
__device__ __align__(16) int     g_blksum[512];
__device__ __align__(16) int     g_blkoff[512];
__device__ __align__(16) int     g_csr_src[N_EDGES];
__device__ __align__(16) float   g_csr_w1[N_EDGES];
__device__ __align__(16) float   g_csr_w2[N_EDGES];
__device__ __align__(16) __half2 g_s1h[(size_t)N_NODES * (F_MID / 2)]; // x@W1, fp16
__device__ __align__(16) float   g_h [(size_t)N_NODES * F_MID];  // agg+bias+leaky
__device__ __align__(16) __half2 g_s2h[(size_t)N_NODES * (F_OUT / 2)]; // h@W2, fp16

// ---------------- CSR construction ------------------------------------------
__global__ void zero_deg_kernel() {
    int i = blockIdx.x * blockDim.x + threadIdx.x;
    if (i < N_NODES) g_deg[i] = 0;
}

__global__ void hist_kernel(const int* __restrict__ dst) {
    int e = blockIdx.x * blockDim.x + threadIdx.x;
    if (e < N_EDGES) atomicAdd(&g_deg[dst[e]], 1);
}

// 3-phase parallel exclusive scan of g_deg -> g_rowptr / g_cursor
__global__ void scan_part_kernel() {            // grid = NB, block = 256
    __shared__ int warp_tot[8];
    const int b = blockIdx.x, tid = threadIdx.x;
    const int lane = tid & 31, w = tid >> 5;
    const int i = b * 256 + tid;
    int v = (i < N_NODES) ? g_deg[i] : 0;
    int x = v;
    #pragma unroll
    for (int off = 1; off < 32; off <<= 1) {
        int y = __shfl_up_sync(0xffffffffu, x, off);
        if (lane >= off) x += y;
    }
    if (lane == 31) warp_tot[w] = x;
    __syncthreads();
    if (w == 0) {
        int t = (lane < 8) ? warp_tot[lane] : 0;
        #pragma unroll
        for (int off = 1; off < 8; off <<= 1) {
            int y = __shfl_up_sync(0xffffffffu, t, off);
            if (lane >= off) t += y;
        }
        if (lane < 8) warp_tot[lane] = t;   // inclusive warp totals
    }
    __syncthreads();
    int excl = x - v + (w > 0 ? warp_tot[w - 1] : 0);
    if (i < N_NODES) g_rowptr[i] = excl;    // block-local exclusive
    if (tid == 255) g_blksum[b] = excl + v; // block total
}

__global__ void scan_blk_kernel() {             // 1 block, 512 threads
    __shared__ int s[512];
    const int tid = threadIdx.x;
    const int nb = (N_NODES + 255) / 256;
    int v = (tid < nb) ? g_blksum[tid] : 0;
    s[tid] = v;
    __syncthreads();
    #pragma unroll
    for (int off = 1; off < 512; off <<= 1) {
        int t = (tid >= off) ? s[tid - off] : 0;
        __syncthreads();
        s[tid] += t;
        __syncthreads();
    }
    g_blkoff[tid] = s[tid] - v;                 // exclusive
}

__global__ void scan_add_kernel() {             // grid = NB, block = 256
    const int b = blockIdx.x;
    const int i = b * 256 + threadIdx.x;
    if (i < N_NODES) {
        int r = g_rowptr[i] + g_blkoff[b];
        g_rowptr[i] = r;
        g_cursor[i] = r;
    }
    if (i == 0) g_rowptr[N_NODES] = N_EDGES;
}

__global__ void scatter_kernel(const int* __restrict__ src,
                               const int* __restrict__ dst,
                               const float* __restrict__ w1,
                               const float* __restrict__ w2) {
    int e = blockIdx.x * blockDim.x + threadIdx.x;
    if (e < N_EDGES) {
        int d = dst[e];
        int p = atomicAdd(&g_cursor[d], 1);
        g_csr_src[p] = src[e];
        g_csr_w1[p]  = w1[e];
        g_csr_w2[p]  = w2[e];
    }
}

// ---------------- TF32 tensor-core GEMM helpers ------------------------------
__device__ __forceinline__ uint32_t f2tf32(float f) {
    uint32_t u = __float_as_uint(f);
    u += 0xFFFu + ((u >> 13) & 1u);
    return u & 0xFFFFE000u;
}

__device__ __forceinline__ void mma_tf32(float* c, const uint32_t* a, const uint32_t* b) {
    asm volatile(
        "mma.sync.aligned.m16n8k8.row.col.f32.tf32.tf32.f32 "
        "{%0,%1,%2,%3}, {%4,%5,%6,%7}, {%8,%9}, {%0,%1,%2,%3};"
        : "+f"(c[0]), "+f"(c[1]), "+f"(c[2]), "+f"(c[3])
        : "r"(a[0]), "r"(a[1]), "r"(a[2]), "r"(a[3]), "r"(b[0]), "r"(b[1]));
}

__device__ __forceinline__ void cp_async16(void* smem, const void* gmem) {
    uint32_t s = (uint32_t)__cvta_generic_to_shared(smem);
    asm volatile("cp.async.cg.shared.global [%0], [%1], 16;"
                 :: "r"(s), "l"(gmem));
}

// ---------------- GEMM1: g_s1h[100000,256](fp16) = x @ W1 --------------------
// BM=128, BN=128, BK=16; 8 warps 4(M) x 2(N); warp tile 32x64.
// Double-buffered cp.async pipeline.
__global__ __launch_bounds__(256) void gemm1_tf32_kernel(const float* __restrict__ A,
                                                         const float* __restrict__ B) {
    constexpr int KDIM = F_IN, NDIM = F_MID, M = N_NODES;
    constexpr int BM = 128, BK = 16;
    constexpr int BKp = 20;
    constexpr int BNp = 132;
    constexpr int T = KDIM / BK;   // 32 k-stages

    __shared__ float As[2][BM * BKp];
    __shared__ float Bs[2][BK * BNp];

    const int tid  = threadIdx.x;
    const int lane = tid & 31;
    const int warp = tid >> 5;
    const int wm   = (warp & 3) * 32;
    const int wn   = (warp >> 2) * 64;
    const int m0   = blockIdx.x * BM;
    const int n0   = blockIdx.y * 128;

    float acc[2][8][4];
    #pragma unroll
    for (int mt = 0; mt < 2; mt++)
        #pragma unroll
        for (int nt = 0; nt < 8; nt++)
            #pragma unroll
            for (int j = 0; j < 4; j++) acc[mt][nt][j] = 0.f;

    // stage loader: A rows beyond M are simply not issued (stale smem only
    // feeds acc rows whose stores are guarded; mma output rows independent).
    auto load_stage = [&](int t, int s) {
        const int k0 = t * BK;
        #pragma unroll
        for (int i = 0; i < 2; i++) {       // A tile: 512 float4
            int c   = tid + i * 256;
            int row = c >> 2;
            int c4  = c & 3;
            if (m0 + row < M)
                cp_async16(&As[s][row * BKp + c4 * 4],
                           &A[(size_t)(m0 + row) * KDIM + k0 + c4 * 4]);
        }
        #pragma unroll
        for (int i = 0; i < 2; i++) {       // B tile: 512 float4
            int c   = tid + i * 256;
            int row = c >> 5;
            int c4  = c & 31;
            cp_async16(&Bs[s][row * BNp + c4 * 4],
                       &B[(size_t)(k0 + row) * NDIM + n0 + c4 * 4]);
        }
        asm volatile("cp.async.commit_group;");
    };

    load_stage(0, 0);
    for (int t = 0; t < T; t++) {
        const int s = t & 1;
        if (t + 1 < T) {
            load_stage(t + 1, s ^ 1);
            asm volatile("cp.async.wait_group 1;");
        } else {
            asm volatile("cp.async.wait_group 0;");
        }
        __syncthreads();

        #pragma unroll
        for (int kk = 0; kk < BK; kk += 8) {
            uint32_t af[2][4], bf[8][2];
            #pragma unroll
            for (int mt = 0; mt < 2; mt++) {
                int r0 = wm + mt * 16 + (lane >> 2);
                int c0 = kk + (lane & 3);
                af[mt][0] = f2tf32(As[s][r0 * BKp + c0]);
                af[mt][1] = f2tf32(As[s][(r0 + 8) * BKp + c0]);
                af[mt][2] = f2tf32(As[s][r0 * BKp + c0 + 4]);
                af[mt][3] = f2tf32(As[s][(r0 + 8) * BKp + c0 + 4]);
            }
            #pragma unroll
            for (int nt = 0; nt < 8; nt++) {
                int col = wn + nt * 8 + (lane >> 2);
                int r   = kk + (lane & 3);
                bf[nt][0] = f2tf32(Bs[s][r * BNp + col]);
                bf[nt][1] = f2tf32(Bs[s][(r + 4) * BNp + col]);
            }
            #pragma unroll
            for (int mt = 0; mt < 2; mt++)
                #pragma unroll
                for (int nt = 0; nt < 8; nt++)
                    mma_tf32(acc[mt][nt], af[mt], bf[nt]);
        }
        __syncthreads();   // all reads of buf s done before t+1 overwrites it
    }

    // epilogue: fp16 pairs; col is even so (col, col+1) -> one half2
    #pragma unroll
    for (int mt = 0; mt < 2; mt++) {
        #pragma unroll
        for (int nt = 0; nt < 8; nt++) {
            int r0  = m0 + wm + mt * 16 + (lane >> 2);
            int col = n0 + wn + nt * 8 + 2 * (lane & 3);
            if (r0 < M)
                g_s1h[((size_t)r0 * NDIM + col) / 2] =
                    __float22half2_rn(make_float2(acc[mt][nt][0], acc[mt][nt][1]));
            if (r0 + 8 < M)
                g_s1h[((size_t)(r0 + 8) * NDIM + col) / 2] =
                    __float22half2_rn(make_float2(acc[mt][nt][2], acc[mt][nt][3]));
        }
    }
}

// ---------------- GEMM2: g_s2h[100000,64](fp16) = g_h @ W2 (tf32) ------------
// BM=128, BN=64, BK=16; 8 warps 4(M) x 2(N); warp tile 32x32.
__global__ __launch_bounds__(256) void gemm2_tf32_kernel(const float* __restrict__ B) {
    constexpr int KDIM = F_MID, NDIM = F_OUT, M = N_NODES;
    constexpr int BM = 128, BK = 16;
    constexpr int BKp = 20;
    constexpr int BNp = 68;

    __shared__ float As[BM * BKp];
    __shared__ float Bs[BK * BNp];

    const int tid  = threadIdx.x;
    const int lane = tid & 31;
    const int warp = tid >> 5;
    const int wm   = (warp & 3) * 32;
    const int wn   = (warp >> 2) * 32;
    const int m0   = blockIdx.x * BM;

    float acc[2][4][4];
    #pragma unroll
    for (int mt = 0; mt < 2; mt++)
        #pragma unroll
        for (int nt = 0; nt < 4; nt++)
            #pragma unroll
            for (int j = 0; j < 4; j++) acc[mt][nt][j] = 0.f;

    for (int k0 = 0; k0 < KDIM; k0 += BK) {
        __syncthreads();
        #pragma unroll
        for (int i = 0; i < 2; i++) {       // A tile: 512 float4
            int c   = tid + i * 256;
            int row = c >> 2;
            int c4  = c & 3;
            float4 v = make_float4(0.f, 0.f, 0.f, 0.f);
            if (m0 + row < M)
                v = *reinterpret_cast<const float4*>(
                        &g_h[(size_t)(m0 + row) * KDIM + k0 + c4 * 4]);
            *reinterpret_cast<float4*>(&As[row * BKp + c4 * 4]) = v;
        }
        {                                   // B tile: 16x64 = 256 float4
            int row = tid >> 4;
            int c4  = tid & 15;
            *reinterpret_cast<float4*>(&Bs[row * BNp + c4 * 4]) =
                *reinterpret_cast<const float4*>(
                    &B[(size_t)(k0 + row) * NDIM + c4 * 4]);
        }
        __syncthreads();

        #pragma unroll
        for (int kk = 0; kk < BK; kk += 8) {
            uint32_t af[2][4], bf[4][2];
            #pragma unroll
            for (int mt = 0; mt < 2; mt++) {
                int r0 = wm + mt * 16 + (lane >> 2);
                int c0 = kk + (lane & 3);
                af[mt][0] = f2tf32(As[r0 * BKp + c0]);
                af[mt][1] = f2tf32(As[(r0 + 8) * BKp + c0]);
                af[mt][2] = f2tf32(As[r0 * BKp + c0 + 4]);
                af[mt][3] = f2tf32(As[(r0 + 8) * BKp + c0 + 4]);
            }
            #pragma unroll
            for (int nt = 0; nt < 4; nt++) {
                int col = wn + nt * 8 + (lane >> 2);
                int r   = kk + (lane & 3);
                bf[nt][0] = f2tf32(Bs[r * BNp + col]);
                bf[nt][1] = f2tf32(Bs[(r + 4) * BNp + col]);
            }
            #pragma unroll
            for (int mt = 0; mt < 2; mt++)
                #pragma unroll
                for (int nt = 0; nt < 4; nt++)
                    mma_tf32(acc[mt][nt], af[mt], bf[nt]);
        }
    }

    #pragma unroll
    for (int mt = 0; mt < 2; mt++) {
        #pragma unroll
        for (int nt = 0; nt < 4; nt++) {
            int r0  = m0 + wm + mt * 16 + (lane >> 2);
            int col = wn + nt * 8 + 2 * (lane & 3);   // even
            if (r0 < M)
                g_s2h[((size_t)r0 * NDIM + col) / 2] =
                    __float22half2_rn(make_float2(acc[mt][nt][0], acc[mt][nt][1]));
            if (r0 + 8 < M)
                g_s2h[((size_t)(r0 + 8) * NDIM + col) / 2] =
                    __float22half2_rn(make_float2(acc[mt][nt][2], acc[mt][nt][3]));
        }
    }
}

// ---------------- layer-1 aggregation: 128 threads/node, half2 gathers ------
__global__ __launch_bounds__(128) void agg1_kernel(const float* __restrict__ b1) {
    const int node = blockIdx.x;
    const int f2   = threadIdx.x;           // 0..127, features 2f2, 2f2+1
    const int beg  = g_rowptr[node];
    const int end  = g_rowptr[node + 1];
    float acc0 = 0.f, acc1 = 0.f;
    int e = beg;
    for (; e + 4 <= end; e += 4) {
        int   s0 = g_csr_src[e],     s1 = g_csr_src[e + 1];
        int   s2 = g_csr_src[e + 2], s3 = g_csr_src[e + 3];
        float w0 = g_csr_w1[e],      w1 = g_csr_w1[e + 1];
        float w2 = g_csr_w1[e + 2],  w3 = g_csr_w1[e + 3];
        float2 v0 = __half22float2(g_s1h[(size_t)s0 * (F_MID / 2) + f2]);
        float2 v1 = __half22float2(g_s1h[(size_t)s1 * (F_MID / 2) + f2]);
        float2 v2 = __half22float2(g_s1h[(size_t)s2 * (F_MID / 2) + f2]);
        float2 v3 = __half22float2(g_s1h[(size_t)s3 * (F_MID / 2) + f2]);
        acc0 += v0.x * w0 + v1.x * w1 + v2.x * w2 + v3.x * w3;
        acc1 += v0.y * w0 + v1.y * w1 + v2.y * w2 + v3.y * w3;
    }
    for (; e < end; e++) {
        float  w = g_csr_w1[e];
        float2 v = __half22float2(g_s1h[(size_t)g_csr_src[e] * (F_MID / 2) + f2]);
        acc0 += v.x * w;
        acc1 += v.y * w;
    }
    acc0 += b1[2 * f2];
    acc1 += b1[2 * f2 + 1];
    g_h[(size_t)node * F_MID + 2 * f2]     = acc0 > 0.f ? acc0 : NEG_SLOPE * acc0;
    g_h[(size_t)node * F_MID + 2 * f2 + 1] = acc1 > 0.f ? acc1 : NEG_SLOPE * acc1;
}

// ---------------- layer-2 aggregation + bias + log_softmax (1 warp/node) ----
__global__ __launch_bounds__(32) void agg2_kernel(const float* __restrict__ b2,
                                                  float* __restrict__ out) {
    const int node = blockIdx.x;
    const int f2   = threadIdx.x;           // 0..31, features 2f2, 2f2+1
    const int beg  = g_rowptr[node];
    const int end  = g_rowptr[node + 1];
    float acc0 = 0.f, acc1 = 0.f;
    int e = beg;
    for (; e + 4 <= end; e += 4) {
        int   s0 = g_csr_src[e],     s1 = g_csr_src[e + 1];
        int   s2 = g_csr_src[e + 2], s3 = g_csr_src[e + 3];
        float w0 = g_csr_w2[e],      w1 = g_csr_w2[e + 1];
        float w2 = g_csr_w2[e + 2],  w3 = g_csr_w2[e + 3];
        float2 v0 = __half22float2(g_s2h[(size_t)s0 * (F_OUT / 2) + f2]);
        float2 v1 = __half22float2(g_s2h[(size_t)s1 * (F_OUT / 2) + f2]);
        float2 v2 = __half22float2(g_s2h[(size_t)s2 * (F_OUT / 2) + f2]);
        float2 v3 = __half22float2(g_s2h[(size_t)s3 * (F_OUT / 2) + f2]);
        acc0 += v0.x * w0 + v1.x * w1 + v2.x * w2 + v3.x * w3;
        acc1 += v0.y * w0 + v1.y * w1 + v2.y * w2 + v3.y * w3;
    }
    for (; e < end; e++) {
        float  w = g_csr_w2[e];
        float2 v = __half22float2(g_s2h[(size_t)g_csr_src[e] * (F_OUT / 2) + f2]);
        acc0 += v.x * w;
        acc1 += v.y * w;
    }
    acc0 += b2[2 * f2];
    acc1 += b2[2 * f2 + 1];

    // log_softmax over 64 features in one warp
    const unsigned FULL = 0xffffffffu;
    float m = fmaxf(acc0, acc1);
    #pragma unroll
    for (int off = 16; off; off >>= 1) m = fmaxf(m, __shfl_xor_sync(FULL, m, off));
    float s = expf(acc0 - m) + expf(acc1 - m);
    #pragma unroll
    for (int off = 16; off; off >>= 1) s += __shfl_xor_sync(FULL, s, off);
    float lse = m + logf(s);

    *reinterpret_cast<float2*>(&out[(size_t)node * F_OUT + 2 * f2]) =
        make_float2(acc0 - lse, acc1 - lse);
}

// ---------------- launch -----------------------------------------------------
extern "C" void kernel_launch(void* const* d_in, const int* in_sizes, int n_in,
                              void* d_out, int out_size) {
    const float* x   = (const float*)d_in[0];
    const int*   src = (const int*)d_in[1];
    const int*   dst = (const int*)d_in[2];
    const float* w1  = (const float*)d_in[3];
    const float* w2  = (const float*)d_in[4];
    const float* W1  = (const float*)d_in[5];
    const float* b1  = (const float*)d_in[6];
    const float* W2  = (const float*)d_in[7];
    const float* b2  = (const float*)d_in[8];
    float* out = (float*)d_out;

    const int EB = (N_EDGES + 255) / 256;
    const int NB = (N_NODES + 255) / 256;

    zero_deg_kernel<<<NB, 256>>>();                 // launch 0
    hist_kernel<<<EB, 256>>>(dst);                  // launch 1
    scan_part_kernel<<<NB, 256>>>();                // launch 2
    scan_blk_kernel<<<1, 512>>>();                  // launch 3
    scan_add_kernel<<<NB, 256>>>();                 // launch 4
    {                                               // launch 5
        dim3 grid((N_NODES + 127) / 128, F_MID / 128);
        gemm1_tf32_kernel<<<grid, 256>>>(x, W1);
    }
    scatter_kernel<<<EB, 256>>>(src, dst, w1, w2);  // launch 6
    agg1_kernel<<<N_NODES, 128>>>(b1);              // launch 7
    gemm2_tf32_kernel<<<(N_NODES + 127) / 128, 256>>>(W2);
    agg2_kernel<<<N_NODES, 32>>>(b2, out);
}